// round 3
// baseline (speedup 1.0000x reference)
#include <cuda_runtime.h>
#include <math.h>

#define BB    32
#define NIN   2312
#define NHID  512
#define NOUT  10
#define TT    350
#define IDXCAP 256            // max active inputs per (b,t) column (mean 115.6, +13.4 sigma)
#define NROW  2313            // 2312 real rows + 1 zero pad row
#define NCOL  (BB * TT)       // 11200

#define THETA  10.0f
#define D_REF  0.36787944117144233f    // exp(-1)
#define C_REF  -54.365636569180905f    // -2*10*e

// ---------------- scratch (device globals; no cudaMalloc allowed) ----------------
__device__ float          g_W1Tc[32 * NROW * 16];     // chunked W1^T: [hc][i][16]   4.74 MB
__device__ unsigned short g_IDX [NCOL * IDXCAP];      // per-column active indices   5.7 MB
__device__ int            g_CNT [NCOL];               // padded counts (multiple of 8)
__device__ float          g_Y1  [NCOL * NHID];        // dense(W1,x), t-major        22.9 MB
__device__ float          g_S1  [NCOL * NHID];        // hidden spikes, t-major      22.9 MB

// ---------------- W1 [h][i] -> chunked W1T [h/16][i][h%16], pad row i=2312 = 0 ----
__global__ void k_prep(const float* __restrict__ W1) {
    __shared__ float s[32][33];
    int i = blockIdx.x * 32 + threadIdx.x;
    int h = blockIdx.y * 32 + threadIdx.y;
    s[threadIdx.y][threadIdx.x] = (i < NIN && h < NHID) ? W1[h * NIN + i] : 0.f;
    __syncthreads();
    int i2 = blockIdx.x * 32 + threadIdx.y;
    int h2 = blockIdx.y * 32 + threadIdx.x;
    if (i2 < NROW) {
        int hc = h2 >> 4, hl = h2 & 15;
        g_W1Tc[((size_t)hc * NROW + i2) * 16 + hl] = s[threadIdx.x][threadIdx.y];
    }
}

// ---------------- fused pack + extract: one warp per (b, 32-t chunk) -------------
// lane owns column (b, t); streams A coalesced, builds bit-words in registers,
// extracts ascending-i index list thread-locally. No cross-thread communication.
__global__ void k_packex(const float* __restrict__ A) {
    int gw   = (blockIdx.x * blockDim.x + threadIdx.x) >> 5;
    int lane = threadIdx.x & 31;
    int b = gw / 11, chunk = gw - b * 11;
    if (b >= BB) return;
    int t = chunk * 32 + lane;
    bool valid = (t < TT);
    int tld = valid ? t : TT - 1;
    const float* Ab = A + (size_t)b * NIN * TT;
    int col = b * TT + t;
    unsigned short* idx = g_IDX + (size_t)(valid ? col : 0) * IDXCAP;
    int cnt = 0;
    for (int ic = 0; ic < 73; ic++) {
        int ibase = ic * 32;
        unsigned w0 = 0, w1 = 0, w2 = 0, w3 = 0;
#pragma unroll
        for (int k4 = 0; k4 < 8; k4++) {
            int i = ibase + k4 * 4;
            if (i + 3 < NIN) {
                float v0 = Ab[(size_t)(i    ) * TT + tld];
                float v1 = Ab[(size_t)(i + 1) * TT + tld];
                float v2 = Ab[(size_t)(i + 2) * TT + tld];
                float v3 = Ab[(size_t)(i + 3) * TT + tld];
                if (v0 > 0.5f) w0 |= 1u << (k4 * 4    );
                if (v1 > 0.5f) w1 |= 1u << (k4 * 4 + 1);
                if (v2 > 0.5f) w2 |= 1u << (k4 * 4 + 2);
                if (v3 > 0.5f) w3 |= 1u << (k4 * 4 + 3);
            } else {
#pragma unroll
                for (int r = 0; r < 4; r++) {
                    int ii = i + r;
                    if (ii < NIN && Ab[(size_t)ii * TT + tld] > 0.5f)
                        w0 |= 1u << (k4 * 4 + r);
                }
            }
        }
        unsigned w = (w0 | w1) | (w2 | w3);
        if (valid) {
            while (w) {
                int bp = __ffs(w) - 1; w &= w - 1;
                if (cnt < IDXCAP) idx[cnt] = (unsigned short)(ibase + bp);
                cnt++;
            }
        }
    }
    if (valid) {
        if (cnt > IDXCAP) cnt = IDXCAP;
        int pad = (cnt + 7) & ~7; if (pad > IDXCAP) pad = IDXCAP;
        for (int j = cnt; j < pad; j++) idx[j] = (unsigned short)(NROW - 1); // zero row
        g_CNT[col] = pad;
    }
}

// ---------------- SpMM: smem-resident W1T slice, 512 threads, 128 cols/pass ------
#define SPMM_SMEM (NROW * 64 + 128 * IDXCAP * 2 + 512)
__global__ void __launch_bounds__(512, 1) k_spmm() {
    extern __shared__ char smraw[];
    float4*         sW = (float4*)smraw;                                 // NROW x 4 float4 (148 KB)
    unsigned short* sI = (unsigned short*)(smraw + NROW * 64);           // 128 x IDXCAP   (64 KB)
    int*            sC = (int*)(smraw + NROW * 64 + 128 * IDXCAP * 2);   // 128
    int tid = threadIdx.x;
    int hc  = blockIdx.y;                 // 32 h-chunks of 16
    int grp = blockIdx.x;                 // 22 groups of 512 columns

    const float4* wsrc = (const float4*)(g_W1Tc + (size_t)hc * NROW * 16);
    for (int i = tid; i < NROW * 4; i += 512) sW[i] = wsrc[i];

    int wid = tid >> 5, lane = tid & 31;
    for (int p = 0; p < 4; p++) {
        int col0 = grp * 512 + p * 128;
        __syncthreads();                                // prev pass done before reuse
        if (tid < 128) sC[tid] = (col0 + tid < NCOL) ? g_CNT[col0 + tid] : 0;
        for (int c = wid; c < 128; c += 16) {
            int col = col0 + c;
            if (col < NCOL) {
                int n = g_CNT[col];                     // padded to multiple of 8
                const uint4* gs = (const uint4*)(g_IDX + (size_t)col * IDXCAP);
                uint4* ds = (uint4*)(sI + c * IDXCAP);
                for (int j = lane; j * 8 < n; j += 32) ds[j] = gs[j];
            }
        }
        __syncthreads();
        int c = tid >> 2, h4 = tid & 3;                 // 4 threads x float4 = 16 h
        int col = col0 + c;
        int n = sC[c];
        const uint2* il2 = (const uint2*)(sI + c * IDXCAP);
        float4 A0 = {0,0,0,0}, A1 = {0,0,0,0}, A2 = {0,0,0,0}, A3 = {0,0,0,0};
        int iters = n >> 2;                             // n multiple of 8 -> even
#pragma unroll 2
        for (int j = 0; j < iters; j++) {
            uint2 pk = il2[j];                          // broadcast over 4 lanes
            int i0 = pk.x & 0xffff, i1 = pk.x >> 16;
            int i2 = pk.y & 0xffff, i3 = pk.y >> 16;
            float4 w0 = sW[i0 * 4 + h4];
            float4 w1 = sW[i1 * 4 + h4];
            float4 w2 = sW[i2 * 4 + h4];
            float4 w3 = sW[i3 * 4 + h4];
            A0.x += w0.x; A0.y += w0.y; A0.z += w0.z; A0.w += w0.w;
            A1.x += w1.x; A1.y += w1.y; A1.z += w1.z; A1.w += w1.w;
            A2.x += w2.x; A2.y += w2.y; A2.z += w2.z; A2.w += w2.w;
            A3.x += w3.x; A3.y += w3.y; A3.z += w3.z; A3.w += w3.w;
        }
        if (col < NCOL) {
            float4 r;
            r.x = (A0.x + A1.x) + (A2.x + A3.x);
            r.y = (A0.y + A1.y) + (A2.y + A3.y);
            r.z = (A0.z + A1.z) + (A2.z + A3.z);
            r.w = (A0.w + A1.w) + (A2.w + A3.w);
            ((float4*)g_Y1)[(size_t)col * 128 + hc * 4 + h4] = r;
        }
    }
}

// ---------------- FIR1 (register-blocked) fused with spike IIR -------------------
#define FPAD  112
#define TROWS (FPAD + 384)    // 496
#define FIR_SMEM ((TROWS * 32 + TT * 32 + 128) * 4)
__global__ void __launch_bounds__(256, 2) k_fir_spike1() {
    extern __shared__ float sm[];
    float* tile = sm;                     // [TROWS][32], zero-padded front/back
    float* usm  = sm + TROWS * 32;        // [350][32]
    float* epsx = usm + TT * 32;          // epsx[i] = eps(i-7), 0 outside [1,99]
    int tid = threadIdx.x;
    int b   = blockIdx.x >> 4;
    int h0  = (blockIdx.x & 15) * 32;

    if (tid < 128) {
        int j = tid - 7;
        epsx[tid] = (j >= 1 && j <= 99) ? (float)((j / 10.0) * exp(1.0 - j / 10.0)) : 0.f;
    }
    for (int i = tid; i < FPAD * 32; i += 256) tile[i] = 0.f;
    for (int i = tid; i < (TROWS - FPAD - TT) * 32; i += 256) tile[(FPAD + TT) * 32 + i] = 0.f;
    for (int i = tid; i < TT * 32; i += 256) {
        int t = i >> 5, hl = i & 31;
        tile[(FPAD + t) * 32 + hl] = g_Y1[((size_t)(b * TT + t)) * NHID + h0 + hl];
    }
    __syncthreads();

    int hl = tid & 31, rg = tid >> 5;
    for (int m = 0; m < 6; m++) {
        int t0 = m * 64 + rg * 8;         // 8 outputs per thread
        if (t0 >= TT) break;              // rg uniform per warp -> no divergence
        float s0=0,s1=0,s2=0,s3=0,s4=0,s5=0,s6=0,s7=0;
        int baserow = FPAD + t0 + 7;
        for (int k0 = 1; k0 <= 105; k0 += 8) {
            float e[15];
#pragma unroll
            for (int i = 0; i < 15; i++) e[i] = epsx[k0 + i];
#pragma unroll
            for (int u = 0; u < 8; u++) {
                float x = tile[(baserow - k0 - u) * 32 + hl];
                s0 = fmaf(e[u    ], x, s0);
                s1 = fmaf(e[u + 1], x, s1);
                s2 = fmaf(e[u + 2], x, s2);
                s3 = fmaf(e[u + 3], x, s3);
                s4 = fmaf(e[u + 4], x, s4);
                s5 = fmaf(e[u + 5], x, s5);
                s6 = fmaf(e[u + 6], x, s6);
                s7 = fmaf(e[u + 7], x, s7);
            }
        }
        float acc[8] = {s0,s1,s2,s3,s4,s5,s6,s7};
#pragma unroll
        for (int r = 0; r < 8; r++) {
            int t = t0 + r;
            if (t < TT) usm[t * 32 + hl] = acc[r];
        }
    }
    __syncthreads();

    if (tid < 32) {                        // per-h refractory IIR over t
        float a = 0.f, rb = 0.f;
        size_t obase = ((size_t)b * TT) * NHID + h0 + tid;
        for (int t = 0; t < TT; t++) {
            float u  = usm[t * 32 + tid] + C_REF * rb;
            float s  = (u >= THETA) ? 1.f : 0.f;
            float an = D_REF * a + s;
            rb = D_REF * rb + D_REF * a;
            a  = an;
            g_S1[obase + (size_t)t * NHID] = s;
        }
    }
}

// ---------------- mm2 + FIR2 + spike2, fused per batch --------------------------
#define TAIL_SMEM ((5120 + 32768 + 4490 + 128) * 4)
__global__ void __launch_bounds__(512, 1) k_tail(const float* __restrict__ W2,
                                                 float* __restrict__ out) {
    extern __shared__ float sm[];
    float* sW2  = sm;                        // [10][512]
    float* sS1  = sm + 5120;                 // [64][512] S1 chunk (reused as U2/S2)
    float* sY2  = sm + 5120 + 32768;         // [99+350][10], front zero-padded
    float* seps = sm + 5120 + 32768 + 4490;  // eps[0..99]
    float* sU2  = sS1;                       // [350][10]
    float* sS2  = sS1 + 3500;                // [10][350]
    int tid = threadIdx.x;
    int b   = blockIdx.x;

    for (int i = tid; i < NOUT * NHID; i += 512) sW2[i] = W2[i];
    if (tid < 128) seps[tid] = (tid >= 1 && tid < 100)
                               ? (float)((tid / 10.0) * exp(1.0 - tid / 10.0)) : 0.f;
    for (int i = tid; i < 99 * NOUT; i += 512) sY2[i] = 0.f;

    int wid = tid >> 5, lane = tid & 31;
    for (int tc = 0; tc < TT; tc += 64) {
        int rows = min(64, TT - tc);
        __syncthreads();
        const float4* src = (const float4*)(g_S1 + ((size_t)(b * TT + tc)) * NHID);
        for (int i = tid; i < rows * 128; i += 512) ((float4*)sS1)[i] = src[i];
        __syncthreads();
        for (int task = wid; task < rows * NOUT; task += 16) {
            int t = task / NOUT, o = task - t * NOUT;
            float acc = 0.f;
            const float* sp = sS1 + t * NHID;
            const float* wp = sW2 + o * NHID;
#pragma unroll 4
            for (int h = lane; h < NHID; h += 32) acc = fmaf(sp[h], wp[h], acc);
#pragma unroll
            for (int ofs = 16; ofs; ofs >>= 1) acc += __shfl_down_sync(0xffffffffu, acc, ofs);
            if (lane == 0) sY2[(99 + tc + t) * NOUT + o] = acc;
        }
    }
    __syncthreads();
    for (int i = tid; i < TT * NOUT; i += 512) {         // FIR2
        int t = i / NOUT, o = i - t * NOUT;
        float acc = 0.f;
#pragma unroll 4
        for (int k = 1; k < 100; k++)
            acc = fmaf(seps[k], sY2[(99 + t - k) * NOUT + o], acc);
        sU2[i] = acc;
    }
    __syncthreads();
    if (tid < NOUT) {                                    // spike2 IIR
        float a = 0.f, rb = 0.f;
        for (int t = 0; t < TT; t++) {
            float u  = sU2[t * NOUT + tid] + C_REF * rb;
            float s  = (u >= THETA) ? 1.f : 0.f;
            float an = D_REF * a + s;
            rb = D_REF * rb + D_REF * a;
            a  = an;
            sS2[tid * TT + t] = s;
        }
    }
    __syncthreads();
    for (int i = tid; i < NOUT * TT; i += 512)
        out[(size_t)b * NOUT * TT + i] = sS2[i];
}

extern "C" void kernel_launch(void* const* d_in, const int* in_sizes, int n_in,
                              void* d_out, int out_size) {
    const float* A  = nullptr;   // spikeInput [B][NIN][T]
    const float* W1 = nullptr;   // [NHID][NIN]
    const float* W2 = nullptr;   // [NOUT][NHID]
    for (int i = 0; i < n_in; i++) {
        if      (in_sizes[i] == BB * NIN * TT) A  = (const float*)d_in[i];
        else if (in_sizes[i] == NHID * NIN)    W1 = (const float*)d_in[i];
        else if (in_sizes[i] == NOUT * NHID)   W2 = (const float*)d_in[i];
    }
    float* out = (float*)d_out;

    cudaFuncSetAttribute(k_spmm,       cudaFuncAttributeMaxDynamicSharedMemorySize, SPMM_SMEM);
    cudaFuncSetAttribute(k_fir_spike1, cudaFuncAttributeMaxDynamicSharedMemorySize, FIR_SMEM);
    cudaFuncSetAttribute(k_tail,       cudaFuncAttributeMaxDynamicSharedMemorySize, TAIL_SMEM);

    k_prep  <<<dim3(73, 16), dim3(32, 32)>>>(W1);
    k_packex<<<44, 256>>>(A);
    k_spmm  <<<dim3(22, 32), 512, SPMM_SMEM>>>();
    k_fir_spike1<<<512, 256, FIR_SMEM>>>();
    k_tail  <<<BB, 512, TAIL_SMEM>>>(W2, out);
}

// round 4
// speedup vs baseline: 1.4108x; 1.4108x over previous
#include <cuda_runtime.h>
#include <math.h>

#define BB    32
#define NIN   2312
#define NHID  512
#define NOUT  10
#define TT    350
#define WPT   73              // ceil(NIN/32)
#define IDXCAP 256            // max active inputs per (b,t) column (mean 115.6, +13.4 sigma)
#define NROW  2313            // 2312 real rows + 1 zero pad row
#define NCOL  (BB * TT)       // 11200

#define THETA  10.0f
#define D_REF  0.36787944117144233f    // exp(-1)
#define C_REF  -54.365636569180905f    // -2*10*e

// ---------------- scratch (device globals; no cudaMalloc allowed) ----------------
__device__ float          g_W1Tc[32 * NROW * 16];     // chunked W1^T: [hc][i][16]   4.74 MB
__device__ unsigned       g_PK  [NCOL * WPT];         // packed spike bits           3.3 MB
__device__ unsigned short g_IDX [NCOL * IDXCAP];      // per-column active indices   5.7 MB
__device__ int            g_CNT [NCOL];               // counts, padded to x8
__device__ float          g_Y1  [NCOL * NHID];        // dense(W1,x), t-major        22.9 MB
__device__ float          g_S1  [NCOL * NHID];        // hidden spikes, t-major      22.9 MB
__device__ float          g_U2  [NCOL * NOUT];        // psp(dense(W2,S1))           0.45 MB

// ---------------- W1 [h][i] -> chunked W1T [h/16][i][h%16], pad row i=2312 = 0 ----
__global__ void k_prep(const float* __restrict__ W1) {
    __shared__ float s[32][33];
    int i = blockIdx.x * 32 + threadIdx.x;
    int h = blockIdx.y * 32 + threadIdx.y;
    s[threadIdx.y][threadIdx.x] = (i < NIN && h < NHID) ? W1[h * NIN + i] : 0.f;
    __syncthreads();
    int i2 = blockIdx.x * 32 + threadIdx.y;
    int h2 = blockIdx.y * 32 + threadIdx.x;
    if (i2 < NROW) {
        int hc = h2 >> 4, hl = h2 & 15;
        g_W1Tc[((size_t)hc * NROW + i2) * 16 + hl] = s[threadIdx.x][threadIdx.y];
    }
}

// ---------------- pack input spikes: [b][i][t] -> bits [b][t][i/32] ----------------
__global__ void k_pack(const float* __restrict__ A) {
    __shared__ unsigned char s[32][33];
    int b  = blockIdx.x;
    int i0 = blockIdx.y * 32;
    int t0 = blockIdx.z * 32;
    int i = i0 + threadIdx.y;
    int t = t0 + threadIdx.x;
    unsigned char bit = 0;
    if (i < NIN && t < TT) bit = (A[((size_t)b * NIN + i) * TT + t] > 0.5f) ? 1 : 0;
    s[threadIdx.y][threadIdx.x] = bit;
    __syncthreads();
    if (threadIdx.y == 0) {
        int t2 = t0 + threadIdx.x;
        if (t2 < TT) {
            unsigned w = 0;
#pragma unroll
            for (int y = 0; y < 32; y++) w |= ((unsigned)s[y][threadIdx.x]) << y;
            g_PK[(b * TT + t2) * WPT + blockIdx.y] = w;
        }
    }
}

// ---------------- per-(b,t) index list, padded to multiple of 8 with zero-row ----
__global__ void k_extract() {
    __shared__ int cnt[WPT];
    __shared__ int off[WPT + 1];
    __shared__ unsigned wsh[WPT];
    int bt = blockIdx.x, tid = threadIdx.x;
    if (tid < WPT) {
        unsigned w = g_PK[bt * WPT + tid];
        wsh[tid] = w; cnt[tid] = __popc(w);
    }
    __syncthreads();
    if (tid == 0) {
        int r = 0;
        for (int j = 0; j < WPT; j++) { off[j] = r; r += cnt[j]; }
        off[WPT] = r;
        int pad = (r + 7) & ~7; if (pad > IDXCAP) pad = IDXCAP;
        g_CNT[bt] = pad;
    }
    __syncthreads();
    if (tid < WPT) {
        int o = off[tid]; unsigned w = wsh[tid];
        while (w) {
            int bp = __ffs(w) - 1; w &= w - 1;
            if (o < IDXCAP) g_IDX[(size_t)bt * IDXCAP + o] = (unsigned short)(tid * 32 + bp);
            o++;
        }
    }
    int total = off[WPT];
    int pad = (total + 7) & ~7; if (pad > IDXCAP) pad = IDXCAP;
    for (int j = total + tid; j < pad; j += blockDim.x)
        g_IDX[(size_t)bt * IDXCAP + j] = (unsigned short)(NROW - 1);  // zero row
}

// ---------------- SpMM: smem weights only, indices via LDG, no staging ----------
#define SPMM_SMEM (NROW * 64)
__global__ void __launch_bounds__(512, 1) k_spmm() {
    extern __shared__ float4 sW[];        // [NROW*4] = 148 KB
    int tid = threadIdx.x;
    int hc  = blockIdx.y;                 // 32 h-chunks of 16
    int grp = blockIdx.x;                 // 22 groups of 512 columns

    const float4* wsrc = (const float4*)(g_W1Tc + (size_t)hc * NROW * 16);
    for (int i = tid; i < NROW * 4; i += 512) sW[i] = wsrc[i];
    __syncthreads();

    int c0 = grp * 512 + (tid >> 2);
    int h4 = tid & 3;
#pragma unroll
    for (int p = 0; p < 4; p++) {
        int col = c0 + p * 128;
        if (col >= NCOL) break;
        int n = g_CNT[col];                                 // multiple of 8
        const uint4* il = (const uint4*)(g_IDX + (size_t)col * IDXCAP);
        float4 a0 = {0,0,0,0}, a1 = {0,0,0,0};
        for (int g = 0; g < n; g += 8) {
            uint4 pk = __ldg(&il[g >> 3]);                  // 8 indices, bcast over 4 lanes
            int i0 = pk.x & 0xffff, i1 = pk.x >> 16;
            int i2 = pk.y & 0xffff, i3 = pk.y >> 16;
            int i4 = pk.z & 0xffff, i5 = pk.z >> 16;
            int i6 = pk.w & 0xffff, i7 = pk.w >> 16;
            float4 w0 = sW[i0 * 4 + h4];
            float4 w1 = sW[i1 * 4 + h4];
            float4 w2 = sW[i2 * 4 + h4];
            float4 w3 = sW[i3 * 4 + h4];
            float4 w4 = sW[i4 * 4 + h4];
            float4 w5 = sW[i5 * 4 + h4];
            float4 w6 = sW[i6 * 4 + h4];
            float4 w7 = sW[i7 * 4 + h4];
            a0.x += w0.x; a0.y += w0.y; a0.z += w0.z; a0.w += w0.w;
            a1.x += w1.x; a1.y += w1.y; a1.z += w1.z; a1.w += w1.w;
            a0.x += w2.x; a0.y += w2.y; a0.z += w2.z; a0.w += w2.w;
            a1.x += w3.x; a1.y += w3.y; a1.z += w3.z; a1.w += w3.w;
            a0.x += w4.x; a0.y += w4.y; a0.z += w4.z; a0.w += w4.w;
            a1.x += w5.x; a1.y += w5.y; a1.z += w5.z; a1.w += w5.w;
            a0.x += w6.x; a0.y += w6.y; a0.z += w6.z; a0.w += w6.w;
            a1.x += w7.x; a1.y += w7.y; a1.z += w7.z; a1.w += w7.w;
        }
        float4 r;
        r.x = a0.x + a1.x; r.y = a0.y + a1.y; r.z = a0.z + a1.z; r.w = a0.w + a1.w;
        ((float4*)g_Y1)[(size_t)col * 128 + hc * 4 + h4] = r;
    }
}

// ---------------- FIR1 (register-blocked) fused with spike IIR -------------------
#define FPAD  112
#define TROWS (FPAD + 384)    // 496
#define FIR_SMEM ((TROWS * 32 + TT * 32 + 128) * 4)
__global__ void __launch_bounds__(256, 2) k_fir_spike1() {
    extern __shared__ float sm[];
    float* tile = sm;                     // [TROWS][32], zero-padded front/back
    float* usm  = sm + TROWS * 32;        // [350][32]
    float* epsx = usm + TT * 32;          // epsx[i] = eps(i-7), 0 outside [1,99]
    int tid = threadIdx.x;
    int b   = blockIdx.x >> 4;
    int h0  = (blockIdx.x & 15) * 32;

    if (tid < 128) {
        int j = tid - 7;
        epsx[tid] = (j >= 1 && j <= 99) ? (float)((j / 10.0) * exp(1.0 - j / 10.0)) : 0.f;
    }
    for (int i = tid; i < FPAD * 32; i += 256) tile[i] = 0.f;
    for (int i = tid; i < (TROWS - FPAD - TT) * 32; i += 256) tile[(FPAD + TT) * 32 + i] = 0.f;
    for (int i = tid; i < TT * 32; i += 256) {
        int t = i >> 5, hl = i & 31;
        tile[(FPAD + t) * 32 + hl] = g_Y1[((size_t)(b * TT + t)) * NHID + h0 + hl];
    }
    __syncthreads();

    int hl = tid & 31, rg = tid >> 5;
    for (int m = 0; m < 6; m++) {
        int t0 = m * 64 + rg * 8;
        if (t0 >= TT) break;
        float s0=0,s1=0,s2=0,s3=0,s4=0,s5=0,s6=0,s7=0;
        int baserow = FPAD + t0 + 7;
        for (int k0 = 1; k0 <= 105; k0 += 8) {
            float e[15];
#pragma unroll
            for (int i = 0; i < 15; i++) e[i] = epsx[k0 + i];
#pragma unroll
            for (int u = 0; u < 8; u++) {
                float x = tile[(baserow - k0 - u) * 32 + hl];
                s0 = fmaf(e[u    ], x, s0);
                s1 = fmaf(e[u + 1], x, s1);
                s2 = fmaf(e[u + 2], x, s2);
                s3 = fmaf(e[u + 3], x, s3);
                s4 = fmaf(e[u + 4], x, s4);
                s5 = fmaf(e[u + 5], x, s5);
                s6 = fmaf(e[u + 6], x, s6);
                s7 = fmaf(e[u + 7], x, s7);
            }
        }
        float acc[8] = {s0,s1,s2,s3,s4,s5,s6,s7};
#pragma unroll
        for (int r = 0; r < 8; r++) {
            int t = t0 + r;
            if (t < TT) usm[t * 32 + hl] = acc[r];
        }
    }
    __syncthreads();

    if (tid < 32) {
        float a = 0.f, rb = 0.f;
        size_t obase = ((size_t)b * TT) * NHID + h0 + tid;
        for (int t = 0; t < TT; t++) {
            float u  = usm[t * 32 + tid] + C_REF * rb;
            float s  = (u >= THETA) ? 1.f : 0.f;
            float an = D_REF * a + s;
            rb = D_REF * rb + D_REF * a;
            a  = an;
            g_S1[obase + (size_t)t * NHID] = s;
        }
    }
}

// ---------------- GEMV2 + FIR2: t-chunked, overlap recompute --------------------
#define TCHUNK 70
#define GEMV_SMEM ((64 * NHID + 169 * NOUT + 128) * 4)
__global__ void __launch_bounds__(512, 1) k_gemv2(const float* __restrict__ W2) {
    extern __shared__ float sm[];
    float* sS1  = sm;                        // [64][512]
    float* sY2  = sm + 64 * NHID;            // [169][10], slot s = row (tc-99)+s
    float* seps = sm + 64 * NHID + 169 * NOUT;
    int tid = threadIdx.x;
    int b   = blockIdx.x;
    int tc  = blockIdx.y * TCHUNK;
    int base = tc - 99;
    int rlo = max(0, base), rhi = tc + TCHUNK;    // rhi <= 350

    if (tid < 128) seps[tid] = (tid >= 1 && tid < 100)
                               ? (float)((tid / 10.0) * exp(1.0 - tid / 10.0)) : 0.f;
    for (int i = tid; i < 169 * NOUT; i += 512) sY2[i] = 0.f;

    int wid = tid >> 5, lane = tid & 31;
    for (int r0 = rlo; r0 < rhi; r0 += 64) {
        int rows = min(64, rhi - r0);
        __syncthreads();
        const float4* src = (const float4*)(g_S1 + ((size_t)(b * TT + r0)) * NHID);
        for (int i = tid; i < rows * 128; i += 512) ((float4*)sS1)[i] = src[i];
        __syncthreads();
        for (int task = wid; task < rows * NOUT; task += 16) {
            int tl = task / NOUT, o = task - tl * NOUT;
            float acc = 0.f;
            const float* sp = sS1 + tl * NHID;
            const float* wp = W2 + o * NHID;
#pragma unroll 4
            for (int h = lane; h < NHID; h += 32) acc = fmaf(sp[h], wp[h], acc);
#pragma unroll
            for (int ofs = 16; ofs; ofs >>= 1) acc += __shfl_down_sync(0xffffffffu, acc, ofs);
            if (lane == 0) sY2[(r0 + tl - base) * NOUT + o] = acc;
        }
    }
    __syncthreads();
    for (int i = tid; i < TCHUNK * NOUT; i += 512) {
        int tl = i / NOUT, o = i - tl * NOUT;
        int t = tc + tl;
        float acc = 0.f;
#pragma unroll 4
        for (int k = 1; k < 100; k++)
            acc = fmaf(seps[k], sY2[(t - k - base) * NOUT + o], acc);
        g_U2[(b * TT + t) * NOUT + o] = acc;
    }
}

// ---------------- spike2 IIR -> final output [B][NOUT][T] ------------------------
__global__ void k_spike2(float* __restrict__ out) {
    int tid = threadIdx.x;
    if (tid >= BB * NOUT) return;
    int b = tid / NOUT, o = tid - b * NOUT;
    float a = 0.f, rb = 0.f;
    for (int t = 0; t < TT; t++) {
        float u  = g_U2[(b * TT + t) * NOUT + o] + C_REF * rb;
        float s  = (u >= THETA) ? 1.f : 0.f;
        float an = D_REF * a + s;
        rb = D_REF * rb + D_REF * a;
        a  = an;
        out[((size_t)b * NOUT + o) * TT + t] = s;
    }
}

extern "C" void kernel_launch(void* const* d_in, const int* in_sizes, int n_in,
                              void* d_out, int out_size) {
    const float* A  = nullptr;   // spikeInput [B][NIN][T]
    const float* W1 = nullptr;   // [NHID][NIN]
    const float* W2 = nullptr;   // [NOUT][NHID]
    for (int i = 0; i < n_in; i++) {
        if      (in_sizes[i] == BB * NIN * TT) A  = (const float*)d_in[i];
        else if (in_sizes[i] == NHID * NIN)    W1 = (const float*)d_in[i];
        else if (in_sizes[i] == NOUT * NHID)   W2 = (const float*)d_in[i];
    }
    float* out = (float*)d_out;

    cudaFuncSetAttribute(k_spmm,       cudaFuncAttributeMaxDynamicSharedMemorySize, SPMM_SMEM);
    cudaFuncSetAttribute(k_fir_spike1, cudaFuncAttributeMaxDynamicSharedMemorySize, FIR_SMEM);
    cudaFuncSetAttribute(k_gemv2,      cudaFuncAttributeMaxDynamicSharedMemorySize, GEMV_SMEM);

    k_prep   <<<dim3(73, 16), dim3(32, 32)>>>(W1);
    k_pack   <<<dim3(BB, WPT, 11), dim3(32, 32)>>>(A);
    k_extract<<<NCOL, 128>>>();
    k_spmm   <<<dim3(22, 32), 512, SPMM_SMEM>>>();
    k_fir_spike1<<<512, 256, FIR_SMEM>>>();
    k_gemv2  <<<dim3(BB, TT / TCHUNK), 512, GEMV_SMEM>>>(W2);
    k_spike2 <<<1, 352>>>(out);
}

// round 5
// speedup vs baseline: 1.4706x; 1.0424x over previous
#include <cuda_runtime.h>
#include <math.h>

#define BB    32
#define NIN   2312
#define NHID  512
#define NOUT  10
#define TT    350
#define WPT   73              // ceil(NIN/32)
#define IDXCAP 256            // max active inputs per (b,t) column (mean 115.6, +13.4 sigma)
#define NROW  2313            // 2312 real rows + 1 zero pad row
#define NCOL  (BB * TT)       // 11200

#define THETA  10.0f
#define D_REF  0.36787944117144233f    // exp(-1)
#define C_REF  -54.365636569180905f    // -2*10*e

// ---------------- scratch (device globals; no cudaMalloc allowed) ----------------
__device__ float          g_W1Tc[64 * NROW * 8];      // chunked W1^T: [hc][i][8]    4.74 MB
__device__ unsigned       g_PK  [NCOL * WPT];         // packed spike bits           3.3 MB
__device__ unsigned short g_IDX [NCOL * IDXCAP + 8];  // per-column indices (+pad)   5.7 MB
__device__ int            g_CNT [NCOL];               // counts, padded to x8
__device__ float          g_Y1  [NCOL * NHID];        // dense(W1,x), t-major        22.9 MB
__device__ float          g_S1  [NCOL * NHID];        // hidden spikes, t-major      22.9 MB
__device__ float          g_U2  [NCOL * NOUT];        // psp(dense(W2,S1))           0.45 MB

// ---------------- W1 [h][i] -> chunked W1T [h/8][i][h%8], pad row i=2312 = 0 ------
__global__ void k_prep(const float* __restrict__ W1) {
    __shared__ float s[32][33];
    int i = blockIdx.x * 32 + threadIdx.x;
    int h = blockIdx.y * 32 + threadIdx.y;
    s[threadIdx.y][threadIdx.x] = (i < NIN && h < NHID) ? W1[h * NIN + i] : 0.f;
    __syncthreads();
    int i2 = blockIdx.x * 32 + threadIdx.y;
    int h2 = blockIdx.y * 32 + threadIdx.x;
    if (i2 < NROW) {
        int hc = h2 >> 3, hl = h2 & 7;
        g_W1Tc[((size_t)hc * NROW + i2) * 8 + hl] = s[threadIdx.x][threadIdx.y];
    }
}

// ---------------- pack input spikes: [b][i][t] -> bits [b][t][i/32] ----------------
__global__ void k_pack(const float* __restrict__ A) {
    __shared__ unsigned char s[32][33];
    int b  = blockIdx.x;
    int i0 = blockIdx.y * 32;
    int t0 = blockIdx.z * 32;
    int i = i0 + threadIdx.y;
    int t = t0 + threadIdx.x;
    unsigned char bit = 0;
    if (i < NIN && t < TT) bit = (A[((size_t)b * NIN + i) * TT + t] > 0.5f) ? 1 : 0;
    s[threadIdx.y][threadIdx.x] = bit;
    __syncthreads();
    if (threadIdx.y == 0) {
        int t2 = t0 + threadIdx.x;
        if (t2 < TT) {
            unsigned w = 0;
#pragma unroll
            for (int y = 0; y < 32; y++) w |= ((unsigned)s[y][threadIdx.x]) << y;
            g_PK[(b * TT + t2) * WPT + blockIdx.y] = w;
        }
    }
}

// ---------------- per-(b,t) index list, padded to multiple of 8 with zero-row ----
__global__ void k_extract() {
    __shared__ int cnt[WPT];
    __shared__ int off[WPT + 1];
    __shared__ unsigned wsh[WPT];
    int bt = blockIdx.x, tid = threadIdx.x;
    if (tid < WPT) {
        unsigned w = g_PK[bt * WPT + tid];
        wsh[tid] = w; cnt[tid] = __popc(w);
    }
    __syncthreads();
    if (tid == 0) {
        int r = 0;
        for (int j = 0; j < WPT; j++) { off[j] = r; r += cnt[j]; }
        off[WPT] = r;
        int pad = (r + 7) & ~7; if (pad > IDXCAP) pad = IDXCAP;
        g_CNT[bt] = pad;
    }
    __syncthreads();
    if (tid < WPT) {
        int o = off[tid]; unsigned w = wsh[tid];
        while (w) {
            int bp = __ffs(w) - 1; w &= w - 1;
            if (o < IDXCAP) g_IDX[(size_t)bt * IDXCAP + o] = (unsigned short)(tid * 32 + bp);
            o++;
        }
    }
    int total = off[WPT];
    int pad = (total + 7) & ~7; if (pad > IDXCAP) pad = IDXCAP;
    for (int j = total + tid; j < pad; j += blockDim.x)
        g_IDX[(size_t)bt * IDXCAP + j] = (unsigned short)(NROW - 1);  // zero row
}

// ---------------- SpMM: 74KB smem weights (2 blocks/SM), prefetched indices ------
#define SPMM_SMEM (NROW * 32)
__global__ void __launch_bounds__(512, 2) k_spmm() {
    extern __shared__ float4 sW[];        // [NROW*2] = 74 KB
    int tid = threadIdx.x;
    int hc  = blockIdx.y;                 // 64 h-chunks of 8
    int grp = blockIdx.x;                 // 22 groups of 512 columns

    const float4* wsrc = (const float4*)(g_W1Tc + (size_t)hc * NROW * 8);
    for (int i = tid; i < NROW * 2; i += 512) sW[i] = wsrc[i];
    __syncthreads();

    int c0 = grp * 512 + (tid >> 1);
    int h4 = tid & 1;
#pragma unroll
    for (int p = 0; p < 2; p++) {
        int col = c0 + p * 256;
        if (col >= NCOL) break;
        int n = g_CNT[col];                                 // multiple of 8
        const uint4* il = (const uint4*)(g_IDX + (size_t)col * IDXCAP);
        int ng = n >> 3;
        float4 a0 = {0,0,0,0}, a1 = {0,0,0,0};
        uint4 pk = __ldg(il);                               // lists padded: +1 read safe
        for (int g = 0; g < ng; g++) {
            uint4 nx = __ldg(&il[g + 1]);                   // prefetch next group
            int i0 = pk.x & 0xffff, i1 = pk.x >> 16;
            int i2 = pk.y & 0xffff, i3 = pk.y >> 16;
            int i4 = pk.z & 0xffff, i5 = pk.z >> 16;
            int i6 = pk.w & 0xffff, i7 = pk.w >> 16;
            float4 w0 = sW[i0 * 2 + h4];
            float4 w1 = sW[i1 * 2 + h4];
            float4 w2 = sW[i2 * 2 + h4];
            float4 w3 = sW[i3 * 2 + h4];
            float4 w4 = sW[i4 * 2 + h4];
            float4 w5 = sW[i5 * 2 + h4];
            float4 w6 = sW[i6 * 2 + h4];
            float4 w7 = sW[i7 * 2 + h4];
            a0.x += w0.x; a0.y += w0.y; a0.z += w0.z; a0.w += w0.w;
            a1.x += w1.x; a1.y += w1.y; a1.z += w1.z; a1.w += w1.w;
            a0.x += w2.x; a0.y += w2.y; a0.z += w2.z; a0.w += w2.w;
            a1.x += w3.x; a1.y += w3.y; a1.z += w3.z; a1.w += w3.w;
            a0.x += w4.x; a0.y += w4.y; a0.z += w4.z; a0.w += w4.w;
            a1.x += w5.x; a1.y += w5.y; a1.z += w5.z; a1.w += w5.w;
            a0.x += w6.x; a0.y += w6.y; a0.z += w6.z; a0.w += w6.w;
            a1.x += w7.x; a1.y += w7.y; a1.z += w7.z; a1.w += w7.w;
            pk = nx;
        }
        float4 r;
        r.x = a0.x + a1.x; r.y = a0.y + a1.y; r.z = a0.z + a1.z; r.w = a0.w + a1.w;
        ((float4*)g_Y1)[(size_t)col * 128 + hc * 2 + h4] = r;
    }
}

// ---------------- FIR1 (register-blocked) fused with spike IIR -------------------
#define FPAD  112
#define TROWS (FPAD + 384)    // 496
#define FIR_SMEM ((TROWS * 32 + TT * 32 + 128) * 4)
__global__ void __launch_bounds__(256, 2) k_fir_spike1() {
    extern __shared__ float sm[];
    float* tile = sm;                     // [TROWS][32], zero-padded front/back
    float* usm  = sm + TROWS * 32;        // [350][32]
    float* epsx = usm + TT * 32;          // epsx[i] = eps(i-7), 0 outside [1,99]
    int tid = threadIdx.x;
    int b   = blockIdx.x >> 4;
    int h0  = (blockIdx.x & 15) * 32;

    if (tid < 128) {
        int j = tid - 7;
        epsx[tid] = (j >= 1 && j <= 99) ? (float)((j / 10.0) * exp(1.0 - j / 10.0)) : 0.f;
    }
    for (int i = tid; i < FPAD * 32; i += 256) tile[i] = 0.f;
    for (int i = tid; i < (TROWS - FPAD - TT) * 32; i += 256) tile[(FPAD + TT) * 32 + i] = 0.f;
    for (int i = tid; i < TT * 32; i += 256) {
        int t = i >> 5, hl = i & 31;
        tile[(FPAD + t) * 32 + hl] = g_Y1[((size_t)(b * TT + t)) * NHID + h0 + hl];
    }
    __syncthreads();

    int hl = tid & 31, rg = tid >> 5;
    for (int m = 0; m < 6; m++) {
        int t0 = m * 64 + rg * 8;
        if (t0 >= TT) break;
        float s0=0,s1=0,s2=0,s3=0,s4=0,s5=0,s6=0,s7=0;
        int baserow = FPAD + t0 + 7;
        for (int k0 = 1; k0 <= 105; k0 += 8) {
            float e[15];
#pragma unroll
            for (int i = 0; i < 15; i++) e[i] = epsx[k0 + i];
#pragma unroll
            for (int u = 0; u < 8; u++) {
                float x = tile[(baserow - k0 - u) * 32 + hl];
                s0 = fmaf(e[u    ], x, s0);
                s1 = fmaf(e[u + 1], x, s1);
                s2 = fmaf(e[u + 2], x, s2);
                s3 = fmaf(e[u + 3], x, s3);
                s4 = fmaf(e[u + 4], x, s4);
                s5 = fmaf(e[u + 5], x, s5);
                s6 = fmaf(e[u + 6], x, s6);
                s7 = fmaf(e[u + 7], x, s7);
            }
        }
        float acc[8] = {s0,s1,s2,s3,s4,s5,s6,s7};
#pragma unroll
        for (int r = 0; r < 8; r++) {
            int t = t0 + r;
            if (t < TT) usm[t * 32 + hl] = acc[r];
        }
    }
    __syncthreads();

    if (tid < 32) {
        float a = 0.f, rb = 0.f;
        size_t obase = ((size_t)b * TT) * NHID + h0 + tid;
        for (int t = 0; t < TT; t++) {
            float u  = usm[t * 32 + tid] + C_REF * rb;
            float s  = (u >= THETA) ? 1.f : 0.f;
            float an = D_REF * a + s;
            rb = D_REF * rb + D_REF * a;
            a  = an;
            g_S1[obase + (size_t)t * NHID] = s;
        }
    }
}

// ---------------- GEMV2 + FIR2: t-chunked, overlap recompute --------------------
#define TCHUNK 70
#define GEMV_SMEM ((64 * NHID + 169 * NOUT + 128) * 4)
__global__ void __launch_bounds__(512, 1) k_gemv2(const float* __restrict__ W2) {
    extern __shared__ float sm[];
    float* sS1  = sm;                        // [64][512]
    float* sY2  = sm + 64 * NHID;            // [169][10], slot s = row (tc-99)+s
    float* seps = sm + 64 * NHID + 169 * NOUT;
    int tid = threadIdx.x;
    int b   = blockIdx.x;
    int tc  = blockIdx.y * TCHUNK;
    int base = tc - 99;
    int rlo = max(0, base), rhi = tc + TCHUNK;    // rhi <= 350

    if (tid < 128) seps[tid] = (tid >= 1 && tid < 100)
                               ? (float)((tid / 10.0) * exp(1.0 - tid / 10.0)) : 0.f;
    for (int i = tid; i < 169 * NOUT; i += 512) sY2[i] = 0.f;

    int wid = tid >> 5, lane = tid & 31;
    for (int r0 = rlo; r0 < rhi; r0 += 64) {
        int rows = min(64, rhi - r0);
        __syncthreads();
        const float4* src = (const float4*)(g_S1 + ((size_t)(b * TT + r0)) * NHID);
        for (int i = tid; i < rows * 128; i += 512) ((float4*)sS1)[i] = src[i];
        __syncthreads();
        for (int task = wid; task < rows * NOUT; task += 16) {
            int tl = task / NOUT, o = task - tl * NOUT;
            float acc = 0.f;
            const float* sp = sS1 + tl * NHID;
            const float* wp = W2 + o * NHID;
#pragma unroll 4
            for (int h = lane; h < NHID; h += 32) acc = fmaf(sp[h], wp[h], acc);
#pragma unroll
            for (int ofs = 16; ofs; ofs >>= 1) acc += __shfl_down_sync(0xffffffffu, acc, ofs);
            if (lane == 0) sY2[(r0 + tl - base) * NOUT + o] = acc;
        }
    }
    __syncthreads();
    for (int i = tid; i < TCHUNK * NOUT; i += 512) {
        int tl = i / NOUT, o = i - tl * NOUT;
        int t = tc + tl;
        float acc = 0.f;
#pragma unroll 4
        for (int k = 1; k < 100; k++)
            acc = fmaf(seps[k], sY2[(t - k - base) * NOUT + o], acc);
        g_U2[(b * TT + t) * NOUT + o] = acc;
    }
}

// ---------------- spike2 IIR (smem-staged, per-batch block) ----------------------
__global__ void __launch_bounds__(256, 4) k_spike2(float* __restrict__ out) {
    __shared__ float su[TT * NOUT];       // U2 for this b, [t][o]
    __shared__ float ss[NOUT * TT];       // spikes, [o][t]
    int b = blockIdx.x, tid = threadIdx.x;
    const float4* src = (const float4*)(g_U2 + (size_t)b * TT * NOUT);
    for (int i = tid; i < TT * NOUT / 2; i += 256) {
        float4 v = src[i];
        su[i * 4] = v.x; su[i * 4 + 1] = v.y; su[i * 4 + 2] = v.z; su[i * 4 + 3] = v.w;
    }
    __syncthreads();
    if (tid < NOUT) {
        float a = 0.f, rb = 0.f;
        for (int t = 0; t < TT; t++) {
            float u  = su[t * NOUT + tid] + C_REF * rb;
            float s  = (u >= THETA) ? 1.f : 0.f;
            float an = D_REF * a + s;
            rb = D_REF * rb + D_REF * a;
            a  = an;
            ss[tid * TT + t] = s;
        }
    }
    __syncthreads();
    for (int i = tid; i < NOUT * TT; i += 256)
        out[(size_t)b * NOUT * TT + i] = ss[i];
}

extern "C" void kernel_launch(void* const* d_in, const int* in_sizes, int n_in,
                              void* d_out, int out_size) {
    const float* A  = nullptr;   // spikeInput [B][NIN][T]
    const float* W1 = nullptr;   // [NHID][NIN]
    const float* W2 = nullptr;   // [NOUT][NHID]
    for (int i = 0; i < n_in; i++) {
        if      (in_sizes[i] == BB * NIN * TT) A  = (const float*)d_in[i];
        else if (in_sizes[i] == NHID * NIN)    W1 = (const float*)d_in[i];
        else if (in_sizes[i] == NOUT * NHID)   W2 = (const float*)d_in[i];
    }
    float* out = (float*)d_out;

    cudaFuncSetAttribute(k_spmm,       cudaFuncAttributeMaxDynamicSharedMemorySize, SPMM_SMEM);
    cudaFuncSetAttribute(k_fir_spike1, cudaFuncAttributeMaxDynamicSharedMemorySize, FIR_SMEM);
    cudaFuncSetAttribute(k_gemv2,      cudaFuncAttributeMaxDynamicSharedMemorySize, GEMV_SMEM);

    k_prep   <<<dim3(73, 16), dim3(32, 32)>>>(W1);
    k_pack   <<<dim3(BB, WPT, 11), dim3(32, 32)>>>(A);
    k_extract<<<NCOL, 128>>>();
    k_spmm   <<<dim3(22, 64), 512, SPMM_SMEM>>>();
    k_fir_spike1<<<512, 256, FIR_SMEM>>>();
    k_gemv2  <<<dim3(BB, TT / TCHUNK), 512, GEMV_SMEM>>>(W2);
    k_spike2 <<<BB, 256>>>(out);
}

// round 6
// speedup vs baseline: 1.7068x; 1.1606x over previous
#include <cuda_runtime.h>
#include <math.h>

#define BB    32
#define NIN   2312
#define NHID  512
#define NOUT  10
#define TT    350
#define WPT   73              // ceil(NIN/32)
#define NCOL  (BB * TT)       // 11200

#define HALF0 1160            // rows [0,1160) -> half 0, [1160,2312) -> half 1
#define HROWS 1164            // per-half rows incl. zero-pad slots
#define IDXC2 160             // per-half index capacity (mean 58, cap at 144 used)
#define CAPU  144

#define THETA  10.0f
#define D_REF  0.36787944117144233f    // exp(-1)
#define C_REF  -54.365636569180905f    // -2*10*e

#define ADDX2(d, a, b) asm("add.rn.f32x2 %0, %1, %2;" : "=l"(d) : "l"(a), "l"(b))

// ---------------- scratch (device globals; no cudaMalloc allowed) ----------------
__device__ float          g_W1Tc[16 * 2 * HROWS * 32];   // [hc][half][local][32]  4.77 MB
__device__ unsigned       g_PK  [NCOL * WPT];            // packed spike bits      3.3 MB
__device__ unsigned short g_IDXA[NCOL * IDXC2 + 16];     // half-0 local indices   3.6 MB
__device__ unsigned short g_IDXB[NCOL * IDXC2 + 16];     // half-1 local indices   3.6 MB
__device__ int            g_CNTA[NCOL];
__device__ int            g_CNTB[NCOL];
__device__ float          g_Y1a [NCOL * NHID];           // partial sums, half 0   22.9 MB
__device__ float          g_Y1b [NCOL * NHID];           // partial sums, half 1   22.9 MB
__device__ float          g_S1  [NCOL * NHID];           // hidden spikes          22.9 MB
__device__ float          g_U2  [NCOL * NOUT];

// ---------------- W1 [h][i] -> [hc=h/32][half][local][hl=h%32] --------------------
__global__ void k_prep(const float* __restrict__ W1) {
    __shared__ float s[32][33];
    int i = blockIdx.x * 32 + threadIdx.x;
    int h = blockIdx.y * 32 + threadIdx.y;
    s[threadIdx.y][threadIdx.x] = (i < NIN && h < NHID) ? W1[h * NIN + i] : 0.f;
    __syncthreads();
    int i2 = blockIdx.x * 32 + threadIdx.y;
    int h2 = blockIdx.y * 32 + threadIdx.x;
    if (i2 < NIN) {
        int half = (i2 >= HALF0);
        int local = i2 - half * HALF0;
        int hc = h2 >> 5, hl = h2 & 31;
        g_W1Tc[((size_t)(hc * 2 + half) * HROWS + local) * 32 + hl] = s[threadIdx.x][threadIdx.y];
    }
}

// zero the pad rows: half0 locals 1160..1163, half1 locals 1152..1163
__global__ void k_zpad() {
    int hc = blockIdx.x;
    int r = threadIdx.x >> 5, hl = threadIdx.x & 31;   // 16 rows x 32
    int half, local;
    if (r < 4) { half = 0; local = 1160 + r; }
    else       { half = 1; local = 1152 + (r - 4); }
    g_W1Tc[((size_t)(hc * 2 + half) * HROWS + local) * 32 + hl] = 0.f;
}

// ---------------- pack input spikes: [b][i][t] -> bits [b][t][i/32] ----------------
__global__ void k_pack(const float* __restrict__ A) {
    __shared__ unsigned char s[32][33];
    int b  = blockIdx.x;
    int i0 = blockIdx.y * 32;
    int t0 = blockIdx.z * 32;
    int i = i0 + threadIdx.y;
    int t = t0 + threadIdx.x;
    unsigned char bit = 0;
    if (i < NIN && t < TT) bit = (A[((size_t)b * NIN + i) * TT + t] > 0.5f) ? 1 : 0;
    s[threadIdx.y][threadIdx.x] = bit;
    __syncthreads();
    if (threadIdx.y == 0) {
        int t2 = t0 + threadIdx.x;
        if (t2 < TT) {
            unsigned w = 0;
#pragma unroll
            for (int y = 0; y < 32; y++) w |= ((unsigned)s[y][threadIdx.x]) << y;
            g_PK[(b * TT + t2) * WPT + blockIdx.y] = w;
        }
    }
}

// ---------------- per-(b,t) local index lists for both halves --------------------
__global__ void k_extract() {
    __shared__ unsigned wsh[WPT];
    __shared__ int cA[WPT], cB[WPT], oA[WPT], oB[WPT];
    __shared__ int totA, totB;
    int bt = blockIdx.x, tid = threadIdx.x;
    if (tid < WPT) {
        unsigned w = g_PK[bt * WPT + tid];
        wsh[tid] = w;
        unsigned maskA = (tid < 36) ? 0xFFFFFFFFu : (tid == 36 ? 0xFFu : 0u);
        cA[tid] = __popc(w & maskA);
        cB[tid] = __popc(w & ~maskA);
    }
    __syncthreads();
    if (tid == 0) { int r = 0; for (int j = 0; j < WPT; j++) { oA[j] = r; r += cA[j]; } totA = r; }
    if (tid == 32){ int r = 0; for (int j = 0; j < WPT; j++) { oB[j] = r; r += cB[j]; } totB = r; }
    __syncthreads();
    if (tid < WPT) {
        unsigned w = wsh[tid];
        int a = oA[tid], b = oB[tid];
        while (w) {
            int bp = __ffs(w) - 1; w &= w - 1;
            int gi = tid * 32 + bp;
            if (gi < HALF0) { if (a < CAPU) g_IDXA[(size_t)bt * IDXC2 + a] = (unsigned short)gi; a++; }
            else            { if (b < CAPU) g_IDXB[(size_t)bt * IDXC2 + b] = (unsigned short)(gi - HALF0); b++; }
        }
    }
    __syncthreads();
    int tA = min(totA, CAPU), pA = min((tA + 7) & ~7, CAPU);
    int tB = min(totB, CAPU), pB = min((tB + 7) & ~7, CAPU);
    if (tid == 0) { g_CNTA[bt] = pA; g_CNTB[bt] = pB; }
    for (int j = tA + tid; j < pA; j += blockDim.x)
        g_IDXA[(size_t)bt * IDXC2 + j] = (unsigned short)1160;   // half-0 zero row
    for (int j = tB + tid; j < pB; j += blockDim.x)
        g_IDXB[(size_t)bt * IDXC2 + j] = (unsigned short)1152;   // half-1 zero row
}

// ---------------- SpMM: 32-wide h rows in smem, conflict-free quarter-warp reads --
#define SPMM_SMEM (HROWS * 128)
#define GGRP 9
#define COLCHUNK 1280
__global__ void __launch_bounds__(512, 1) k_spmm() {
    extern __shared__ char smraw[];
    const ulonglong2* sW = (const ulonglong2*)smraw;   // HROWS rows x 128 B
    int tid  = threadIdx.x;
    int hc   = blockIdx.y >> 1;
    int half = blockIdx.y & 1;

    const float4* wsrc = (const float4*)(g_W1Tc + (size_t)(hc * 2 + half) * HROWS * 32);
    float4* sWf = (float4*)smraw;
    for (int i = tid; i < HROWS * 8; i += 512) sWf[i] = wsrc[i];
    __syncthreads();

    const unsigned short* IDX = half ? g_IDXB : g_IDXA;
    const int*            CNT = half ? g_CNTB : g_CNTA;
    float*                Y   = half ? g_Y1b  : g_Y1a;

    int h4    = tid & 7;
    int cbase = blockIdx.x * COLCHUNK + (tid >> 3);
    for (int p = 0; p < 20; p++) {
        int col = cbase + p * 64;
        if (col >= NCOL) break;
        int ng = CNT[col] >> 3;
        const uint4* il = (const uint4*)(IDX + (size_t)col * IDXC2);
        unsigned long long a0x = 0, a0y = 0, a1x = 0, a1y = 0;
        if (ng) {
            uint4 pk  = __ldg(il);
            uint4 pk1 = __ldg(il + 1);
            for (int g = 0; g < ng; g++) {
                uint4 nx = __ldg(il + g + 2);                  // prefetch depth 2
                int i0 = pk.x & 0xffff, i1 = pk.x >> 16;
                int i2 = pk.y & 0xffff, i3 = pk.y >> 16;
                int i4 = pk.z & 0xffff, i5 = pk.z >> 16;
                int i6 = pk.w & 0xffff, i7 = pk.w >> 16;
                ulonglong2 w0 = sW[i0 * 8 + h4];               // quarter-warp = 1 row, 0 conflicts
                ulonglong2 w1 = sW[i1 * 8 + h4];
                ulonglong2 w2 = sW[i2 * 8 + h4];
                ulonglong2 w3 = sW[i3 * 8 + h4];
                ulonglong2 w4 = sW[i4 * 8 + h4];
                ulonglong2 w5 = sW[i5 * 8 + h4];
                ulonglong2 w6 = sW[i6 * 8 + h4];
                ulonglong2 w7 = sW[i7 * 8 + h4];
                ADDX2(a0x, a0x, w0.x); ADDX2(a0y, a0y, w0.y);
                ADDX2(a1x, a1x, w1.x); ADDX2(a1y, a1y, w1.y);
                ADDX2(a0x, a0x, w2.x); ADDX2(a0y, a0y, w2.y);
                ADDX2(a1x, a1x, w3.x); ADDX2(a1y, a1y, w3.y);
                ADDX2(a0x, a0x, w4.x); ADDX2(a0y, a0y, w4.y);
                ADDX2(a1x, a1x, w5.x); ADDX2(a1y, a1y, w5.y);
                ADDX2(a0x, a0x, w6.x); ADDX2(a0y, a0y, w6.y);
                ADDX2(a1x, a1x, w7.x); ADDX2(a1y, a1y, w7.y);
                pk = pk1; pk1 = nx;
            }
        }
        float2 p0 = *(float2*)&a0x, q0 = *(float2*)&a0y;
        float2 p1 = *(float2*)&a1x, q1 = *(float2*)&a1y;
        float4 r;
        r.x = p0.x + p1.x; r.y = p0.y + p1.y;
        r.z = q0.x + q1.x; r.w = q0.y + q1.y;
        ((float4*)Y)[(size_t)col * 128 + hc * 8 + h4] = r;
    }
}

// ---------------- FIR1 (register-blocked) fused with spike IIR -------------------
#define FPAD  112
#define TROWS (FPAD + 384)    // 496
#define FIR_SMEM ((TROWS * 32 + TT * 32 + 128) * 4)
__global__ void __launch_bounds__(256, 2) k_fir_spike1() {
    extern __shared__ float sm[];
    float* tile = sm;                     // [TROWS][32], zero-padded front/back
    float* usm  = sm + TROWS * 32;        // [350][32]
    float* epsx = usm + TT * 32;          // epsx[i] = eps(i-7), 0 outside [1,99]
    int tid = threadIdx.x;
    int b   = blockIdx.x >> 4;
    int h0  = (blockIdx.x & 15) * 32;

    if (tid < 128) {
        int j = tid - 7;
        epsx[tid] = (j >= 1 && j <= 99) ? (float)((j / 10.0) * exp(1.0 - j / 10.0)) : 0.f;
    }
    for (int i = tid; i < FPAD * 32; i += 256) tile[i] = 0.f;
    for (int i = tid; i < (TROWS - FPAD - TT) * 32; i += 256) tile[(FPAD + TT) * 32 + i] = 0.f;
    for (int i = tid; i < TT * 32; i += 256) {
        int t = i >> 5, hl = i & 31;
        size_t off = ((size_t)(b * TT + t)) * NHID + h0 + hl;
        tile[(FPAD + t) * 32 + hl] = g_Y1a[off] + g_Y1b[off];
    }
    __syncthreads();

    int hl = tid & 31, rg = tid >> 5;
    for (int m = 0; m < 6; m++) {
        int t0 = m * 64 + rg * 8;
        if (t0 >= TT) break;
        float s0=0,s1=0,s2=0,s3=0,s4=0,s5=0,s6=0,s7=0;
        int baserow = FPAD + t0 + 7;
        for (int k0 = 1; k0 <= 105; k0 += 8) {
            float e[15];
#pragma unroll
            for (int i = 0; i < 15; i++) e[i] = epsx[k0 + i];
#pragma unroll
            for (int u = 0; u < 8; u++) {
                float x = tile[(baserow - k0 - u) * 32 + hl];
                s0 = fmaf(e[u    ], x, s0);
                s1 = fmaf(e[u + 1], x, s1);
                s2 = fmaf(e[u + 2], x, s2);
                s3 = fmaf(e[u + 3], x, s3);
                s4 = fmaf(e[u + 4], x, s4);
                s5 = fmaf(e[u + 5], x, s5);
                s6 = fmaf(e[u + 6], x, s6);
                s7 = fmaf(e[u + 7], x, s7);
            }
        }
        float acc[8] = {s0,s1,s2,s3,s4,s5,s6,s7};
#pragma unroll
        for (int r = 0; r < 8; r++) {
            int t = t0 + r;
            if (t < TT) usm[t * 32 + hl] = acc[r];
        }
    }
    __syncthreads();

    if (tid < 32) {
        float a = 0.f, rb = 0.f;
        size_t obase = ((size_t)b * TT) * NHID + h0 + tid;
        for (int t = 0; t < TT; t++) {
            float u  = usm[t * 32 + tid] + C_REF * rb;
            float s  = (u >= THETA) ? 1.f : 0.f;
            float an = D_REF * a + s;
            rb = D_REF * rb + D_REF * a;
            a  = an;
            g_S1[obase + (size_t)t * NHID] = s;
        }
    }
}

// ---------------- GEMV2 + FIR2: t-chunked, overlap recompute --------------------
#define TCHUNK 70
#define GEMV_SMEM ((64 * NHID + 169 * NOUT + 128) * 4)
__global__ void __launch_bounds__(512, 1) k_gemv2(const float* __restrict__ W2) {
    extern __shared__ float sm[];
    float* sS1  = sm;                        // [64][512]
    float* sY2  = sm + 64 * NHID;            // [169][10], slot s = row (tc-99)+s
    float* seps = sm + 64 * NHID + 169 * NOUT;
    int tid = threadIdx.x;
    int b   = blockIdx.x;
    int tc  = blockIdx.y * TCHUNK;
    int base = tc - 99;
    int rlo = max(0, base), rhi = tc + TCHUNK;

    if (tid < 128) seps[tid] = (tid >= 1 && tid < 100)
                               ? (float)((tid / 10.0) * exp(1.0 - tid / 10.0)) : 0.f;
    for (int i = tid; i < 169 * NOUT; i += 512) sY2[i] = 0.f;

    int wid = tid >> 5, lane = tid & 31;
    for (int r0 = rlo; r0 < rhi; r0 += 64) {
        int rows = min(64, rhi - r0);
        __syncthreads();
        const float4* src = (const float4*)(g_S1 + ((size_t)(b * TT + r0)) * NHID);
        for (int i = tid; i < rows * 128; i += 512) ((float4*)sS1)[i] = src[i];
        __syncthreads();
        for (int task = wid; task < rows * NOUT; task += 16) {
            int tl = task / NOUT, o = task - tl * NOUT;
            float acc = 0.f;
            const float* sp = sS1 + tl * NHID;
            const float* wp = W2 + o * NHID;
#pragma unroll 4
            for (int h = lane; h < NHID; h += 32) acc = fmaf(sp[h], wp[h], acc);
#pragma unroll
            for (int ofs = 16; ofs; ofs >>= 1) acc += __shfl_down_sync(0xffffffffu, acc, ofs);
            if (lane == 0) sY2[(r0 + tl - base) * NOUT + o] = acc;
        }
    }
    __syncthreads();
    for (int i = tid; i < TCHUNK * NOUT; i += 512) {
        int tl = i / NOUT, o = i - tl * NOUT;
        int t = tc + tl;
        float acc = 0.f;
#pragma unroll 4
        for (int k = 1; k < 100; k++)
            acc = fmaf(seps[k], sY2[(t - k - base) * NOUT + o], acc);
        g_U2[(b * TT + t) * NOUT + o] = acc;
    }
}

// ---------------- spike2 IIR (smem-staged, per-batch block) ----------------------
__global__ void __launch_bounds__(256, 4) k_spike2(float* __restrict__ out) {
    __shared__ float su[TT * NOUT];
    __shared__ float ss[NOUT * TT];
    int b = blockIdx.x, tid = threadIdx.x;
    const float4* src = (const float4*)(g_U2 + (size_t)b * TT * NOUT);
    for (int i = tid; i < TT * NOUT / 2; i += 256) {
        float4 v = src[i];
        su[i * 4] = v.x; su[i * 4 + 1] = v.y; su[i * 4 + 2] = v.z; su[i * 4 + 3] = v.w;
    }
    __syncthreads();
    if (tid < NOUT) {
        float a = 0.f, rb = 0.f;
        for (int t = 0; t < TT; t++) {
            float u  = su[t * NOUT + tid] + C_REF * rb;
            float s  = (u >= THETA) ? 1.f : 0.f;
            float an = D_REF * a + s;
            rb = D_REF * rb + D_REF * a;
            a  = an;
            ss[tid * TT + t] = s;
        }
    }
    __syncthreads();
    for (int i = tid; i < NOUT * TT; i += 256)
        out[(size_t)b * NOUT * TT + i] = ss[i];
}

extern "C" void kernel_launch(void* const* d_in, const int* in_sizes, int n_in,
                              void* d_out, int out_size) {
    const float* A  = nullptr;   // spikeInput [B][NIN][T]
    const float* W1 = nullptr;   // [NHID][NIN]
    const float* W2 = nullptr;   // [NOUT][NHID]
    for (int i = 0; i < n_in; i++) {
        if      (in_sizes[i] == BB * NIN * TT) A  = (const float*)d_in[i];
        else if (in_sizes[i] == NHID * NIN)    W1 = (const float*)d_in[i];
        else if (in_sizes[i] == NOUT * NHID)   W2 = (const float*)d_in[i];
    }
    float* out = (float*)d_out;

    cudaFuncSetAttribute(k_spmm,       cudaFuncAttributeMaxDynamicSharedMemorySize, SPMM_SMEM);
    cudaFuncSetAttribute(k_fir_spike1, cudaFuncAttributeMaxDynamicSharedMemorySize, FIR_SMEM);
    cudaFuncSetAttribute(k_gemv2,      cudaFuncAttributeMaxDynamicSharedMemorySize, GEMV_SMEM);

    k_prep   <<<dim3(73, 16), dim3(32, 32)>>>(W1);
    k_zpad   <<<16, 512>>>();
    k_pack   <<<dim3(BB, WPT, 11), dim3(32, 32)>>>(A);
    k_extract<<<NCOL, 128>>>();
    k_spmm   <<<dim3(GGRP, 32), 512, SPMM_SMEM>>>();
    k_fir_spike1<<<512, 256, FIR_SMEM>>>();
    k_gemv2  <<<dim3(BB, TT / TCHUNK), 512, GEMV_SMEM>>>(W2);
    k_spike2 <<<BB, 256>>>(out);
}